// round 2
// baseline (speedup 1.0000x reference)
#include <cuda_runtime.h>

// Stacked spectral filter, exploiting diagonal Lambda:
//   y = U^T x                         (GEMM1)
//   w[j,:] = g(lam_j) * y[j,:]        (fused epilogue of GEMM1)
//   out = alpha*x + U w               (GEMM2)
// g(l) = sum_i 4*c_i/(a_i-b_i)^2 * relu((a_i-l)(l-b_i))

#define BM 64
#define BN 64
#define BK 16
#define BMP 68   // padded BM for transposed A tile in GEMM2 (16B-aligned rows)

// scratch for w = g * (U^T x)   [N, F] = [2048, 256]
__device__ float g_w[2048 * 256];

// ---------------------------------------------------------------------------
// GEMM1: W[j,f] = g(lam_j) * sum_k U[k,j] * X[k,f]
// A-tile = U[k, j]  (j contiguous -> coalesced, stored as As[k][j] directly)
// ---------------------------------------------------------------------------
__global__ __launch_bounds__(256, 2)
void k1_utx_scale(const float* __restrict__ U, const float* __restrict__ X,
                  const float* __restrict__ lam,
                  const float* __restrict__ a, const float* __restrict__ b,
                  const float* __restrict__ c, int nfilt,
                  int N, int F)
{
    __shared__ __align__(16) float As[2][BK][BM];
    __shared__ __align__(16) float Bs[2][BK][BN];

    const int tid = threadIdx.x;
    const int tx = tid & 15;        // 0..15 -> 4 cols each
    const int ty = tid >> 4;        // 0..15 -> 4 rows each
    const int m0 = blockIdx.x * BM; // j
    const int n0 = blockIdx.y * BN; // f

    const int lk = tid >> 4;         // 0..15  (k within tile)
    const int lc = (tid & 15) << 2;  // 0..60  (col within tile, float4)

    float acc[4][4] = {};

    // preload tile 0
    {
        float4 av = *(const float4*)(U + (size_t)lk * N + m0 + lc);
        float4 bv = *(const float4*)(X + (size_t)lk * F + n0 + lc);
        *(float4*)&As[0][lk][lc] = av;
        *(float4*)&Bs[0][lk][lc] = bv;
    }
    __syncthreads();

    const int nk = N / BK;
    for (int t = 0; t < nk; ++t) {
        const int cur = t & 1;
        float4 av, bv;
        const bool more = (t + 1 < nk);
        if (more) {
            const int k0 = (t + 1) * BK;
            av = *(const float4*)(U + (size_t)(k0 + lk) * N + m0 + lc);
            bv = *(const float4*)(X + (size_t)(k0 + lk) * F + n0 + lc);
        }
#pragma unroll
        for (int kk = 0; kk < BK; ++kk) {
            float4 a4 = *(const float4*)&As[cur][kk][ty << 2];
            float4 b4 = *(const float4*)&Bs[cur][kk][tx << 2];
            float ar[4] = {a4.x, a4.y, a4.z, a4.w};
            float br[4] = {b4.x, b4.y, b4.z, b4.w};
#pragma unroll
            for (int i = 0; i < 4; ++i)
#pragma unroll
                for (int j = 0; j < 4; ++j)
                    acc[i][j] += ar[i] * br[j];
        }
        if (more) {
            *(float4*)&As[cur ^ 1][lk][lc] = av;
            *(float4*)&Bs[cur ^ 1][lk][lc] = bv;
        }
        __syncthreads();
    }

    // epilogue: scale each row by g(lam_row)
#pragma unroll
    for (int i = 0; i < 4; ++i) {
        const int row = m0 + (ty << 2) + i;
        const float lv = lam[(size_t)row * N + row];
        float g = 0.f;
#pragma unroll 4
        for (int tf = 0; tf < nfilt; ++tf) {
            const float at = a[tf], bt = b[tf];
            float d = (at - lv) * (lv - bt);
            d = d > 0.f ? d : 0.f;
            const float ab = at - bt;
            g += (4.f * c[tf] / (ab * ab)) * d;
        }
        float* wrow = g_w + (size_t)row * F + n0 + (tx << 2);
#pragma unroll
        for (int j = 0; j < 4; ++j)
            wrow[j] = g * acc[i][j];
    }
}

// ---------------------------------------------------------------------------
// GEMM2: out[n,f] = alpha * X[n,f] + sum_j U[n,j] * W[j,f]
// A-tile = U[n, j] (j contiguous) stored transposed As[j][n] for the k-loop
// ---------------------------------------------------------------------------
__global__ __launch_bounds__(256, 2)
void k2_uw(const float* __restrict__ U, const float* __restrict__ X,
           const float* __restrict__ alpha,
           float* __restrict__ out, int N, int F)
{
    __shared__ __align__(16) float As[2][BK][BMP];
    __shared__ __align__(16) float Bs[2][BK][BN];

    const int tid = threadIdx.x;
    const int tx = tid & 15;
    const int ty = tid >> 4;
    const int m0 = blockIdx.x * BM; // n (output row)
    const int n0 = blockIdx.y * BN; // f

    // A loader: 64 rows x 16 cols, one float4 per thread, transposed store
    const int ar = tid >> 2;          // 0..63  row within tile
    const int ac = (tid & 3) << 2;    // 0,4,8,12  k within tile

    // B loader (same as kernel 1)
    const int lk = tid >> 4;
    const int lc = (tid & 15) << 2;

    float acc[4][4] = {};

    {
        float4 uv = *(const float4*)(U + (size_t)(m0 + ar) * N + ac);
        As[0][ac + 0][ar] = uv.x;
        As[0][ac + 1][ar] = uv.y;
        As[0][ac + 2][ar] = uv.z;
        As[0][ac + 3][ar] = uv.w;
        float4 bv = *(const float4*)(g_w + (size_t)lk * F + n0 + lc);
        *(float4*)&Bs[0][lk][lc] = bv;
    }
    __syncthreads();

    const int nk = N / BK;
    for (int t = 0; t < nk; ++t) {
        const int cur = t & 1;
        float4 uv, bv;
        const bool more = (t + 1 < nk);
        if (more) {
            const int k0 = (t + 1) * BK;
            uv = *(const float4*)(U + (size_t)(m0 + ar) * N + k0 + ac);
            bv = *(const float4*)(g_w + (size_t)(k0 + lk) * F + n0 + lc);
        }
#pragma unroll
        for (int kk = 0; kk < BK; ++kk) {
            float4 a4 = *(const float4*)&As[cur][kk][ty << 2];
            float4 b4 = *(const float4*)&Bs[cur][kk][tx << 2];
            float ar4[4] = {a4.x, a4.y, a4.z, a4.w};
            float br4[4] = {b4.x, b4.y, b4.z, b4.w};
#pragma unroll
            for (int i = 0; i < 4; ++i)
#pragma unroll
                for (int j = 0; j < 4; ++j)
                    acc[i][j] += ar4[i] * br4[j];
        }
        if (more) {
            As[cur ^ 1][ac + 0][ar] = uv.x;
            As[cur ^ 1][ac + 1][ar] = uv.y;
            As[cur ^ 1][ac + 2][ar] = uv.z;
            As[cur ^ 1][ac + 3][ar] = uv.w;
            *(float4*)&Bs[cur ^ 1][lk][lc] = bv;
        }
        __syncthreads();
    }

    const float al = alpha[0];
#pragma unroll
    for (int i = 0; i < 4; ++i) {
        const int row = m0 + (ty << 2) + i;
        const float* xrow = X + (size_t)row * F + n0 + (tx << 2);
        float* orow = out + (size_t)row * F + n0 + (tx << 2);
#pragma unroll
        for (int j = 0; j < 4; ++j)
            orow[j] = al * xrow[j] + acc[i][j];
    }
}

// ---------------------------------------------------------------------------
extern "C" void kernel_launch(void* const* d_in, const int* in_sizes, int n_in,
                              void* d_out, int out_size)
{
    const float* X     = (const float*)d_in[0];  // [N,F]
    const float* Lam   = (const float*)d_in[1];  // [N,N] (diagonal in practice)
    const float* U     = (const float*)d_in[2];  // [N,N]
    const float* a     = (const float*)d_in[3];  // [K]
    const float* b     = (const float*)d_in[4];  // [K]
    const float* c     = (const float*)d_in[5];  // [K]
    const float* alpha = (const float*)d_in[6];  // [1]
    // d_in[7] = edge_index: unused by the reference

    const int nfilt = in_sizes[3];
    // N from lam element count (N*N), F from x element count (N*F)
    int N = 1;
    {
        long s = in_sizes[1];
        long lo = 1, hi = 65536;
        while (lo < hi) { long mid = (lo + hi) >> 1; if (mid * mid < s) lo = mid + 1; else hi = mid; }
        N = (int)lo;
    }
    const int F = in_sizes[0] / N;

    dim3 blk(256);
    dim3 grid(N / BM, F / BN);

    k1_utx_scale<<<grid, blk>>>(U, X, Lam, a, b, c, nfilt, N, F);
    k2_uw<<<grid, blk>>>(U, X, alpha, (float*)d_out, N, F);
}

// round 4
// speedup vs baseline: 2.5721x; 2.5721x over previous
#include <cuda_runtime.h>
#include <cuda_bf16.h>
#include <cstdint>

// ============================================================================
// out = alpha*x + U * diag(g(lam)) * U^T * x       (Lambda diagonal)
// g(l) = sum_i 4*c_i/(a_i-b_i)^2 * relu((a_i-l)(l-b_i))
//
// Engine: warp-level mma.sync m16n8k16 (bf16 in, fp32 accum) — the tensor path
// that compiles for plain sm_103 (tcgen05 needs the 'a' target the harness
// doesn't use). Precision restored with hi/lo splitting, 3 MMAs per product:
//   D += Ah*Bh + Ah*Bl + Al*Bh        (lo*lo term ~2^-18, dropped)
//
//   prep:  U -> Uhi/Ulo (row-major) + Uthi/Utlo (transposed);
//          X -> Xthi/Xtlo (transposed);  g[] from diag(lam)
//   GEMM1 (mode 0): Wt[f,j] = sum_k Xt[f,k]*Ut[j,k]; epilogue *g[j], store
//                   Wt as bf16 hi/lo
//   GEMM2 (mode 1): out[n,f] = alpha*x[n,f] + sum_j U[n,j]*Wt[f,j]
// ============================================================================

#define NDIM 2048
#define FDIM 256
#define KDIM 2048          // contraction length for both GEMMs
#define BT   64            // CTA tile (M and N)
#define KT   64            // k-tile (64 bf16 = 128B row -> SW128 atoms)
#define NKT  (KDIM / KT)   // 32

// dynamic smem: 1KB align pad + 2 stages x (Ah 8K | Al 8K | Bh 8K | Bl 8K)
#define STAGE_BYTES 32768
#define SMEM_DYN    (1024 + 2 * STAGE_BYTES)

// ------------------------- device scratch (no cudaMalloc) -------------------
__device__ __align__(16) __nv_bfloat16 g_Uhi [NDIM * NDIM];
__device__ __align__(16) __nv_bfloat16 g_Ulo [NDIM * NDIM];
__device__ __align__(16) __nv_bfloat16 g_Uthi[NDIM * NDIM];
__device__ __align__(16) __nv_bfloat16 g_Utlo[NDIM * NDIM];
__device__ __align__(16) __nv_bfloat16 g_Xthi[FDIM * NDIM];
__device__ __align__(16) __nv_bfloat16 g_Xtlo[FDIM * NDIM];
__device__ __align__(16) __nv_bfloat16 g_Wthi[FDIM * NDIM];
__device__ __align__(16) __nv_bfloat16 g_Wtlo[FDIM * NDIM];
__device__ float g_g[NDIM];

// ------------------------------- helpers ------------------------------------
__device__ __forceinline__ unsigned s2u(const void* p) {
    unsigned a;
    asm("{ .reg .u64 t; cvta.to.shared.u64 t, %1; cvt.u32.u64 %0, t; }" : "=r"(a) : "l"(p));
    return a;
}
__device__ __forceinline__ unsigned swz(unsigned o) { return o ^ ((o >> 3) & 0x70); }

__device__ __forceinline__ void cpa16(unsigned s, const void* g) {
    asm volatile("cp.async.cg.shared.global [%0], [%1], 16;" :: "r"(s), "l"(g));
}
__device__ __forceinline__ void ldm_x4(unsigned* r, unsigned addr) {
    asm volatile("ldmatrix.sync.aligned.m8n8.x4.shared.b16 {%0,%1,%2,%3}, [%4];"
                 : "=r"(r[0]), "=r"(r[1]), "=r"(r[2]), "=r"(r[3]) : "r"(addr));
}
__device__ __forceinline__ void mma16816(float* d, const unsigned* a, const unsigned* b) {
    asm volatile("mma.sync.aligned.m16n8k16.row.col.f32.bf16.bf16.f32 "
                 "{%0,%1,%2,%3}, {%4,%5,%6,%7}, {%8,%9}, {%0,%1,%2,%3};"
                 : "+f"(d[0]), "+f"(d[1]), "+f"(d[2]), "+f"(d[3])
                 : "r"(a[0]), "r"(a[1]), "r"(a[2]), "r"(a[3]), "r"(b[0]), "r"(b[1]));
}

// ------------------------------ prep kernels --------------------------------
__global__ void prep_g_k(const float* __restrict__ lam, const float* __restrict__ a,
                         const float* __restrict__ b, const float* __restrict__ c, int nf) {
    int j = blockIdx.x * blockDim.x + threadIdx.x;
    if (j >= NDIM) return;
    float lv = lam[(size_t)j * NDIM + j];
    float g = 0.f;
    for (int i = 0; i < nf; ++i) {
        float at = a[i], bt = b[i];
        float d = (at - lv) * (lv - bt);
        d = d > 0.f ? d : 0.f;
        float ab = at - bt;
        g += (4.f * c[i] / (ab * ab)) * d;
    }
    g_g[j] = g;
}

__global__ void prep_U_k(const float* __restrict__ U) {
    __shared__ float t[32][33];
    const int bx = blockIdx.x * 32, by = blockIdx.y * 32;
    const int tx = threadIdx.x, ty = threadIdx.y;
#pragma unroll
    for (int i = 0; i < 4; ++i) {
        int r = ty + i * 8;
        float v = U[(size_t)(by + r) * NDIM + bx + tx];
        t[r][tx] = v;
        __nv_bfloat16 h = __float2bfloat16(v);
        size_t o = (size_t)(by + r) * NDIM + bx + tx;
        g_Uhi[o] = h;
        g_Ulo[o] = __float2bfloat16(v - __bfloat162float(h));
    }
    __syncthreads();
#pragma unroll
    for (int i = 0; i < 4; ++i) {
        int r = ty + i * 8;
        float v = t[tx][r];                            // U[by+tx, bx+r]
        __nv_bfloat16 h = __float2bfloat16(v);
        size_t o = (size_t)(bx + r) * NDIM + by + tx;  // Ut[bx+r, by+tx]
        g_Uthi[o] = h;
        g_Utlo[o] = __float2bfloat16(v - __bfloat162float(h));
    }
}

__global__ void prep_X_k(const float* __restrict__ X) {
    __shared__ float t[32][33];
    const int bx = blockIdx.x * 32, by = blockIdx.y * 32;   // bx over F, by over N
    const int tx = threadIdx.x, ty = threadIdx.y;
#pragma unroll
    for (int i = 0; i < 4; ++i) {
        int r = ty + i * 8;
        t[r][tx] = X[(size_t)(by + r) * FDIM + bx + tx];
    }
    __syncthreads();
#pragma unroll
    for (int i = 0; i < 4; ++i) {
        int r = ty + i * 8;
        float v = t[tx][r];                            // X[by+tx, bx+r]
        __nv_bfloat16 h = __float2bfloat16(v);
        size_t o = (size_t)(bx + r) * NDIM + by + tx;  // Xt[bx+r, by+tx]
        g_Xthi[o] = h;
        g_Xtlo[o] = __float2bfloat16(v - __bfloat162float(h));
    }
}

// --------------------------- mma.sync GEMM kernel ---------------------------
// C[m0+.., n0+..] = A[m, k] * B[n, k]^T  over K=2048, A/B bf16 hi/lo.
// mode 0: A=Xt, B=Ut; epilogue scales col j by g[j], writes Wt hi/lo.
// mode 1: A=U,  B=Wt; epilogue out = alpha*X + D.
__global__ __launch_bounds__(128, 2)
void gemm_mma(int mode, const float* __restrict__ X,
              const float* __restrict__ alpha, float* __restrict__ out)
{
    extern __shared__ char smem_raw[];
    const unsigned sb = (s2u(smem_raw) + 1023u) & ~1023u;

    const int tid = threadIdx.x;
    const int wid = tid >> 5, lane = tid & 31;
    const int warp_m = wid & 1, warp_n = wid >> 1;
    const int m0 = blockIdx.x * BT, n0 = blockIdx.y * BT;

    const __nv_bfloat16 *Ah, *Al, *Bh, *Bl;
    if (mode == 0) { Ah = g_Xthi; Al = g_Xtlo; Bh = g_Uthi; Bl = g_Utlo; }
    else           { Ah = g_Uhi;  Al = g_Ulo;  Bh = g_Wthi; Bl = g_Wtlo; }

    // -------- load plan: 16 cp.async x 16B per thread per stage --------
    const __nv_bfloat16* srcs[4] = {
        Ah + (size_t)m0 * KDIM, Al + (size_t)m0 * KDIM,
        Bh + (size_t)n0 * KDIM, Bl + (size_t)n0 * KDIM };
    unsigned soff[16];
    unsigned goff[16];
#pragma unroll
    for (int i = 0; i < 16; ++i) {
        int arr = i >> 2;
        int l = (i & 3) * 128 + tid;       // 0..511
        int row = l >> 3, c = l & 7;
        soff[i] = arr * 8192 + swz(row * 128 + c * 16);
        goff[i] = row * KDIM + c * 8;
    }

    auto load_tile = [&](int t, int stage) {
        const unsigned st = sb + stage * STAGE_BYTES;
        const unsigned kb = t * KT;
#pragma unroll
        for (int i = 0; i < 16; ++i)
            cpa16(st + soff[i], srcs[i >> 2] + goff[i] + kb);
        asm volatile("cp.async.commit_group;" ::: "memory");
    };

    // -------- ldmatrix address bases (within-tile byte offsets) --------
    unsigned abase[2], bbase[2];
#pragma unroll
    for (int mf = 0; mf < 2; ++mf) {
        int rowA = warp_m * 32 + mf * 16 + ((lane >> 3) & 1) * 8 + (lane & 7);
        abase[mf] = rowA * 128 + (lane >> 4) * 16;
    }
#pragma unroll
    for (int nf2 = 0; nf2 < 2; ++nf2) {
        int rowB = warp_n * 32 + nf2 * 16 + ((lane >> 4) & 1) * 8 + (lane & 7);
        bbase[nf2] = rowB * 128 + ((lane >> 3) & 1) * 16;
    }

    float acc[2][4][4] = {};

    load_tile(0, 0);
    for (int t = 0; t < NKT; ++t) {
        if (t + 1 < NKT) {
            load_tile(t + 1, (t + 1) & 1);
            asm volatile("cp.async.wait_group 1;" ::: "memory");
        } else {
            asm volatile("cp.async.wait_group 0;" ::: "memory");
        }
        __syncthreads();

        const unsigned stA = sb + (t & 1) * STAGE_BYTES;
        const unsigned stB = stA + 16384;
#pragma unroll
        for (int ks = 0; ks < 4; ++ks) {
            unsigned ah[2][4], al[2][4], bh[2][4], bl[2][4];
#pragma unroll
            for (int mf = 0; mf < 2; ++mf) {
                ldm_x4(ah[mf], stA + swz(abase[mf] + ks * 32));
                ldm_x4(al[mf], stA + 8192 + swz(abase[mf] + ks * 32));
            }
#pragma unroll
            for (int nf2 = 0; nf2 < 2; ++nf2) {
                ldm_x4(bh[nf2], stB + swz(bbase[nf2] + ks * 32));
                ldm_x4(bl[nf2], stB + 8192 + swz(bbase[nf2] + ks * 32));
            }
#pragma unroll
            for (int mf = 0; mf < 2; ++mf)
#pragma unroll
                for (int nf = 0; nf < 4; ++nf) {
                    const unsigned* bhp = &bh[nf >> 1][(nf & 1) * 2];
                    const unsigned* blp = &bl[nf >> 1][(nf & 1) * 2];
                    mma16816(acc[mf][nf], ah[mf], bhp);
                    mma16816(acc[mf][nf], ah[mf], blp);
                    mma16816(acc[mf][nf], al[mf], bhp);
                }
        }
        __syncthreads();
    }

    // ------------------------------ epilogue --------------------------------
    const int rbase = m0 + warp_m * 32 + (lane >> 2);
    const int cbase0 = n0 + warp_n * 32 + (lane & 3) * 2;

    if (mode == 0) {
#pragma unroll
        for (int mf = 0; mf < 2; ++mf)
#pragma unroll
            for (int nf = 0; nf < 4; ++nf) {
                const int cb = cbase0 + nf * 8;
                const float g0 = g_g[cb], g1 = g_g[cb + 1];
#pragma unroll
                for (int h = 0; h < 2; ++h) {
                    const int row = rbase + mf * 16 + h * 8;
                    float v0 = acc[mf][nf][h * 2 + 0] * g0;
                    float v1 = acc[mf][nf][h * 2 + 1] * g1;
                    __nv_bfloat16 h0 = __float2bfloat16(v0);
                    __nv_bfloat16 h1 = __float2bfloat16(v1);
                    __nv_bfloat162 hv; hv.x = h0; hv.y = h1;
                    __nv_bfloat162 lv;
                    lv.x = __float2bfloat16(v0 - __bfloat162float(h0));
                    lv.y = __float2bfloat16(v1 - __bfloat162float(h1));
                    *(__nv_bfloat162*)(g_Wthi + (size_t)row * NDIM + cb) = hv;
                    *(__nv_bfloat162*)(g_Wtlo + (size_t)row * NDIM + cb) = lv;
                }
            }
    } else {
        const float av = alpha[0];
#pragma unroll
        for (int mf = 0; mf < 2; ++mf)
#pragma unroll
            for (int nf = 0; nf < 4; ++nf) {
                const int cb = cbase0 + nf * 8;
#pragma unroll
                for (int h = 0; h < 2; ++h) {
                    const int row = rbase + mf * 16 + h * 8;
                    const float2 xv = *(const float2*)(X + (size_t)row * FDIM + cb);
                    float2 o;
                    o.x = av * xv.x + acc[mf][nf][h * 2 + 0];
                    o.y = av * xv.y + acc[mf][nf][h * 2 + 1];
                    *(float2*)(out + (size_t)row * FDIM + cb) = o;
                }
            }
    }
}

// ---------------------------------------------------------------------------
extern "C" void kernel_launch(void* const* d_in, const int* in_sizes, int n_in,
                              void* d_out, int out_size)
{
    const float* X     = (const float*)d_in[0];  // [N,F]
    const float* Lam   = (const float*)d_in[1];  // [N,N] diagonal
    const float* U     = (const float*)d_in[2];  // [N,N]
    const float* a     = (const float*)d_in[3];
    const float* b     = (const float*)d_in[4];
    const float* c     = (const float*)d_in[5];
    const float* alpha = (const float*)d_in[6];
    // d_in[7] = edge_index (unused by the reference math)
    const int nf = in_sizes[3];

    static bool attr_set = false;
    if (!attr_set) {
        cudaFuncSetAttribute(gemm_mma, cudaFuncAttributeMaxDynamicSharedMemorySize, SMEM_DYN);
        attr_set = true;
    }

    prep_g_k<<<NDIM / 256, 256>>>(Lam, a, b, c, nf);
    dim3 bt(32, 8);
    prep_X_k<<<dim3(FDIM / 32, NDIM / 32), bt>>>(X);
    prep_U_k<<<dim3(NDIM / 32, NDIM / 32), bt>>>(U);

    // GEMM1: M=FDIM(256) x N=NDIM(2048):  grid 4 x 32
    gemm_mma<<<dim3(FDIM / BT, NDIM / BT), 128, SMEM_DYN>>>(0, X, alpha, (float*)d_out);
    // GEMM2: M=NDIM(2048) x N=FDIM(256):  grid 32 x 4
    gemm_mma<<<dim3(NDIM / BT, FDIM / BT), 128, SMEM_DYN>>>(1, X, alpha, (float*)d_out);
}